// round 13
// baseline (speedup 1.0000x reference)
#include <cuda_runtime.h>

#define NBLK 128
#define TPB  512
#define TILE 128
#define NRED 17          // reducer blocks; 17*16 = 272 float4 elements
#define EPSV 1e-10f

__device__ __align__(16) float4 g_partial4[NBLK][272];   // 136 tiles x 2 float4
__device__ __align__(16) float4 g_gram4[272];
__device__ __align__(16) float2 g_T[1024];
__device__ unsigned g_arrive;    // monotonic; +128 per launch
__device__ unsigned g_reddone;   // monotonic; +17  per launch
__device__ unsigned g_tready;    // monotonic; +1   per launch

__device__ __forceinline__ unsigned long long pk2(float lo, float hi) {
    unsigned long long r;
    asm("mov.b64 %0, {%1, %2};" : "=l"(r) : "f"(lo), "f"(hi));
    return r;
}
__device__ __forceinline__ unsigned long long fma2(unsigned long long a,
                                                   unsigned long long b,
                                                   unsigned long long c) {
    unsigned long long d;
    asm("fma.rn.f32x2 %0, %1, %2, %3;" : "=l"(d) : "l"(a), "l"(b), "l"(c));
    return d;
}
__device__ __forceinline__ float2 upk2(unsigned long long v) {
    float lo, hi;
    asm("mov.b64 {%0, %1}, %2;" : "=f"(lo), "=f"(hi) : "l"(v));
    return make_float2(lo, hi);
}
__device__ __forceinline__ float red2(unsigned long long v) {
    float2 f = upk2(v);
    return f.x + f.y;
}

__global__ __launch_bounds__(TPB, 1) void k_all(const float2* __restrict__ x,
                                                float2* __restrict__ y) {
    __shared__ __align__(16) char smem[45056];   // [0,32K) xs | [32K,44K) AUX
    __shared__ float invd[32];
    int tid = threadIdx.x;
    int blk = blockIdx.x;

    float2 (*xs)[32] = (float2(*)[32])smem;      // 128 x 32 float2, resident
    char* AUX = smem + 32768;                    // 12KB: pbuf / Rs / packed T planes

    // ================= phase 1: stage x tile, Hermitian partial Gram ========
    const float4* src = (const float4*)(x + (size_t)blk * TILE * 32);
    {
        float4* dst = (float4*)smem;
#pragma unroll
        for (int t = 0; t < 4; t++) dst[tid + TPB * t] = src[tid + TPB * t];
    }
    __syncthreads();

    {
        int gid = tid >> 8;          // m-group: rows 0-63 / 64-127
        int t8  = tid & 255;
        bool active = (t8 < 136);    // 136 upper-triangular 2x2 tiles
        int i0 = 0, j0 = 0;
        if (active) {
            int tt = t8, ti = 0;
            while (tt >= 16 - ti) { tt -= 16 - ti; ti++; }
            i0 = ti * 2;
            j0 = (ti + tt) * 2;
        }
        // packed accumulators: lanes = rows (m, m+1)
        unsigned long long z = pk2(0.f, 0.f);
        unsigned long long r00 = z, i00v = z, r01 = z, i01v = z;
        unsigned long long r10 = z, i10v = z, r11 = z, i11v = z;
        if (active) {
            int mbase = gid * 64;
#pragma unroll 4
            for (int mm = 0; mm < 64; mm += 2) {
                float4 am  = *(const float4*)&xs[mbase + mm][i0];
                float4 am1 = *(const float4*)&xs[mbase + mm + 1][i0];
                float4 bm  = *(const float4*)&xs[mbase + mm][j0];
                float4 bm1 = *(const float4*)&xs[mbase + mm + 1][j0];
                unsigned long long ar0 = pk2(am.x, am1.x);
                unsigned long long ai0 = pk2(am.y, am1.y);
                unsigned long long an0 = pk2(-am.y, -am1.y);
                unsigned long long ar1 = pk2(am.z, am1.z);
                unsigned long long ai1 = pk2(am.w, am1.w);
                unsigned long long an1 = pk2(-am.w, -am1.w);
                unsigned long long br0 = pk2(bm.x, bm1.x);
                unsigned long long bi0 = pk2(bm.y, bm1.y);
                unsigned long long br1 = pk2(bm.z, bm1.z);
                unsigned long long bi1 = pk2(bm.w, bm1.w);
                // conj(a)*b per 2x2 tile entry
                r00  = fma2(ar0, br0, fma2(ai0, bi0, r00));
                i00v = fma2(ar0, bi0, fma2(an0, br0, i00v));
                r01  = fma2(ar0, br1, fma2(ai0, bi1, r01));
                i01v = fma2(ar0, bi1, fma2(an0, br1, i01v));
                r10  = fma2(ar1, br0, fma2(ai1, bi0, r10));
                i10v = fma2(ar1, bi0, fma2(an1, br0, i10v));
                r11  = fma2(ar1, br1, fma2(ai1, bi1, r11));
                i11v = fma2(ar1, bi1, fma2(an1, br1, i11v));
            }
        }
        float a00x = red2(r00), a00y = red2(i00v);
        float a01x = red2(r01), a01y = red2(i01v);
        float a10x = red2(r10), a10y = red2(i10v);
        float a11x = red2(r11), a11y = red2(i11v);

        float2* P = (float2*)AUX;    // 4 x 136 float2 combine buffer
        if (gid == 1 && active) {
            P[0 * 136 + t8] = make_float2(a00x, a00y);
            P[1 * 136 + t8] = make_float2(a01x, a01y);
            P[2 * 136 + t8] = make_float2(a10x, a10y);
            P[3 * 136 + t8] = make_float2(a11x, a11y);
        }
        __syncthreads();
        if (gid == 0 && active) {
            float2 q;
            q = P[0 * 136 + t8]; a00x += q.x; a00y += q.y;
            q = P[1 * 136 + t8]; a01x += q.x; a01y += q.y;
            q = P[2 * 136 + t8]; a10x += q.x; a10y += q.y;
            q = P[3 * 136 + t8]; a11x += q.x; a11y += q.y;
            float4* out = g_partial4[blk];
            out[t8 * 2]     = make_float4(a00x, a00y, a01x, a01y);
            out[t8 * 2 + 1] = make_float4(a10x, a10y, a11x, a11y);
        }
    }

    __threadfence();          // release partial stores
    __syncthreads();
    unsigned rep = 0;
    if (tid == 0) {
        unsigned v = atomicAdd(&g_arrive, 1u);
        rep = (v >> 7) + 1u;  // launch index; arrive target = rep*128
    }

    // ============ distributed reduce: 17 blocks, warp-per-element ===========
    if (blk < NRED) {
        if (tid == 0) {
            unsigned target = rep << 7;
            while ((int)(*(volatile unsigned*)&g_arrive - target) < 0) { }
            __threadfence();  // acquire partials
        }
        __syncthreads();
        int w = tid >> 5, l = tid & 31;
        int e = blk * 16 + w;                       // 0..271
        const float4* gp4 = (const float4*)g_partial4;
        float4 p  = gp4[(size_t)l * 272 + e];
        float4 q1 = gp4[(size_t)(l + 32) * 272 + e];
        float4 q2 = gp4[(size_t)(l + 64) * 272 + e];
        float4 q3 = gp4[(size_t)(l + 96) * 272 + e];
        p.x = ((p.x + q1.x) + q2.x) + q3.x;
        p.y = ((p.y + q1.y) + q2.y) + q3.y;
        p.z = ((p.z + q1.z) + q2.z) + q3.z;
        p.w = ((p.w + q1.w) + q2.w) + q3.w;
#pragma unroll
        for (int off = 16; off > 0; off >>= 1) {
            p.x += __shfl_xor_sync(0xffffffffu, p.x, off);
            p.y += __shfl_xor_sync(0xffffffffu, p.y, off);
            p.z += __shfl_xor_sync(0xffffffffu, p.z, off);
            p.w += __shfl_xor_sync(0xffffffffu, p.w, off);
        }
        if (l == 0) g_gram4[e] = p;
        __threadfence();
        __syncthreads();
        if (tid == 0) atomicAdd(&g_reddone, 1u);
    }

    // ================= phase 2: block 0 solve ===============================
    if (blk == 0) {
        if (tid == 0) {
            unsigned target = rep * NRED;
            while ((int)(*(volatile unsigned*)&g_reddone - target) < 0) { }
            __threadfence();  // acquire g_gram
        }
        __syncthreads();
        // overlays: Gs = xs rows 0..31, Ss = xs rows 32..63, Rs = AUX
        float2 (*Gs)[32] = (float2(*)[32])smem;
        float2 (*Ss)[32] = (float2(*)[32])(smem + 8192);
        float2 (*Rs)[32] = (float2(*)[32])AUX;

        // load + Hermitian mirror G into smem
        if (tid < 136) {
            int tt = tid, ti = 0;
            while (tt >= 16 - ti) { tt -= 16 - ti; ti++; }
            int i0 = ti * 2;
            int j0 = (ti + tt) * 2;
            float4 v0 = g_gram4[tid * 2];
            float4 v1 = g_gram4[tid * 2 + 1];
            Gs[i0][j0]         = make_float2(v0.x, v0.y);
            Gs[i0][j0 + 1]     = make_float2(v0.z, v0.w);
            Gs[i0 + 1][j0]     = make_float2(v1.x, v1.y);
            Gs[i0 + 1][j0 + 1] = make_float2(v1.z, v1.w);
            if (i0 != j0) {
                Gs[j0][i0]         = make_float2(v0.x, -v0.y);
                Gs[j0][i0 + 1]     = make_float2(v1.x, -v1.y);
                Gs[j0 + 1][i0]     = make_float2(v0.z, -v0.w);
                Gs[j0 + 1][i0 + 1] = make_float2(v1.z, -v1.w);
            }
        }
        __syncthreads();

        // ---- register+shfl Cholesky (upper), warp 0, lane = column k -------
        if (tid < 32) {
            int k = tid;
            float2 a[32];
#pragma unroll
            for (int i = 0; i < 32; i++) a[i] = Gs[i][k];
#pragma unroll
            for (int j = 0; j < 32; j++) {
                float d = __shfl_sync(0xffffffffu, a[j].x, j) + EPSV;
                float inv = rsqrtf(d);
                float rjj = d * inv;                       // sqrt(d)
                float rx, ry;
                if (k > j)       { rx = a[j].x * inv; ry = a[j].y * inv; }
                else if (k == j) { rx = rjj; ry = 0.f; invd[j] = inv; }
                else             { rx = 0.f; ry = 0.f; }
                Rs[j][k] = make_float2(rx, ry);
                // a[i] -= conj(R[j][i]) * R[j][k]  for i > j
#pragma unroll
                for (int i = j + 1; i < 32; i++) {
                    float bx = __shfl_sync(0xffffffffu, rx, i);
                    float by = __shfl_sync(0xffffffffu, ry, i);
                    a[i].x -= bx * rx + by * ry;
                    a[i].y -= bx * ry - by * rx;
                }
            }
        }
        __syncthreads();

        // ---- register back-substitution: S11 (lanes 0-15), S22 (16-31) ----
        if (tid < 32) {
            int half = tid >> 4;
            int j = tid & 15;
            int base = half * 16;
            float2 s[16];
#pragma unroll
            for (int i = 15; i >= 0; i--) {
                if (i == j) {
                    s[i] = make_float2(invd[base + i], 0.f);
                } else if (i < j) {
                    float ax = 0.f, ay = 0.f;
#pragma unroll
                    for (int k = i + 1; k < 16; k++) {
                        float2 sv = (k <= j) ? s[k] : make_float2(0.f, 0.f);
                        float2 rv = Rs[base + i][base + k];
                        ax += rv.x * sv.x - rv.y * sv.y;
                        ay += rv.x * sv.y + rv.y * sv.x;
                    }
                    float inv = invd[base + i];
                    s[i] = make_float2(-ax * inv, -ay * inv);
                }
            }
#pragma unroll
            for (int i = 0; i < 16; i++)
                if (i <= j) Ss[base + i][base + j] = s[i];
        }
        __syncthreads();

        // Tmp = R12 * S22   (S22 upper-tri: k <= j; unrolled + predicated)
        float2 (*Tmp)[16] = (float2(*)[16])smem;
        if (tid < 256) {
            int i = tid >> 4, j = tid & 15;
            float ax = 0.f, ay = 0.f;
#pragma unroll
            for (int k = 0; k < 16; k++) {
                if (k <= j) {
                    float2 rv = Rs[i][16 + k];
                    float2 sv = Ss[16 + k][16 + j];
                    ax += rv.x * sv.x - rv.y * sv.y;
                    ay += rv.x * sv.y + rv.y * sv.x;
                }
            }
            Tmp[i][j] = make_float2(ax, ay);
        }
        __syncthreads();
        // S12 = -S11 * Tmp   (S11 upper-tri: k >= i; unrolled + predicated)
        if (tid < 256) {
            int i = tid >> 4, j = tid & 15;
            float ax = 0.f, ay = 0.f;
#pragma unroll
            for (int k = 0; k < 16; k++) {
                if (k >= i) {
                    float2 sv = Ss[i][k];
                    float2 tv = Tmp[k][j];
                    ax += sv.x * tv.x - sv.y * tv.y;
                    ay += sv.x * tv.y + sv.y * tv.x;
                }
            }
            Ss[i][16 + j] = make_float2(-ax, -ay);
        }
        __syncthreads();

        // write T (lower triangle = 0)
        for (int t = tid; t < 1024; t += TPB) {
            int r = t >> 5, c = t & 31;
            g_T[t] = (r <= c) ? Ss[r][c] : make_float2(0.f, 0.f);
        }
        __threadfence();
        __syncthreads();
        if (tid == 0) atomicAdd(&g_tready, 1u);

        // reload xs rows 0..63 (clobbered by Gs/Ss/Tmp); rows 64..127 intact
        ((float4*)smem)[tid]       = src[tid];
        ((float4*)smem)[tid + 512] = src[tid + 512];
    } else {
        if (tid == 0) {
            while ((int)(*(volatile unsigned*)&g_tready - rep) < 0) { }
            __threadfence();  // acquire T
        }
        __syncthreads();
    }

    // ================= phase 3: apply  Y = X * T  (packed f32x2) ============
    {
        unsigned long long (*P1)[32] = (unsigned long long(*)[32])AUX;           // (tr0,tr1)
        unsigned long long (*P2)[32] = (unsigned long long(*)[32])(AUX + 4096);  // (ti0,ti1)
        unsigned long long (*P3)[32] = (unsigned long long(*)[32])(AUX + 8192);  // (-ti0,-ti1)
        {
            int k2 = tid >> 5, jj = tid & 31;   // 512 threads = 16 k-pairs x 32 cols
            float2 v0 = g_T[(2 * k2) * 32 + jj];
            float2 v1 = g_T[(2 * k2 + 1) * 32 + jj];
            P1[k2][jj] = pk2(v0.x, v1.x);
            P2[k2][jj] = pk2(v0.y, v1.y);
            P3[k2][jj] = pk2(-v0.y, -v1.y);
        }
        __syncthreads();

        int j  = tid & 31;
        int r0 = (tid >> 5) * 8;   // 16 warps x 8 rows = 128 rows

        unsigned long long accx[8], accy[8];
        unsigned long long z = pk2(0.f, 0.f);
#pragma unroll
        for (int r = 0; r < 8; r++) { accx[r] = z; accy[r] = z; }

#pragma unroll
        for (int k2 = 0; k2 < 16; k2++) {
            unsigned long long p1 = P1[k2][j];
            unsigned long long p2 = P2[k2][j];
            unsigned long long p3 = P3[k2][j];
#pragma unroll
            for (int r = 0; r < 8; r++) {
                float4 a = *(const float4*)&xs[r0 + r][2 * k2];  // (re0,im0,re1,im1)
                unsigned long long arr = pk2(a.x, a.z);
                unsigned long long aii = pk2(a.y, a.w);
                accx[r] = fma2(arr, p1, accx[r]);
                accx[r] = fma2(aii, p3, accx[r]);
                accy[r] = fma2(arr, p2, accy[r]);
                accy[r] = fma2(aii, p1, accy[r]);
            }
        }

        size_t base = (size_t)blk * TILE + r0;
#pragma unroll
        for (int r = 0; r < 8; r++) {
            float2 fx = upk2(accx[r]);
            float2 fy = upk2(accy[r]);
            y[(base + r) * 32 + j] = make_float2(fx.x + fx.y, fy.x + fy.y);
        }
    }
}

// ---------------------------------------------------------------------------
extern "C" void kernel_launch(void* const* d_in, const int* in_sizes, int n_in,
                              void* d_out, int out_size) {
    const float2* x = (const float2*)d_in[0];
    float2* y = (float2*)d_out;
    (void)in_sizes; (void)n_in; (void)out_size;

    k_all<<<NBLK, TPB>>>(x, y);
}

// round 14
// speedup vs baseline: 1.1838x; 1.1838x over previous
#include <cuda_runtime.h>

#define NBLK 128
#define TPB  512
#define TILE 128
#define NRED 17          // reducer blocks; 17*16 = 272 float4 elements
#define EPSV 1e-10f

__device__ __align__(16) float4 g_partial4[NBLK][272];   // 136 tiles x 2 float4
__device__ __align__(16) float4 g_gram4[272];
__device__ __align__(16) float2 g_T[1024];
__device__ unsigned g_arrive;    // monotonic; +128 per launch
__device__ unsigned g_reddone;   // monotonic; +17  per launch
__device__ unsigned g_tready;    // monotonic; +1   per launch

__device__ __forceinline__ unsigned long long pk2(float lo, float hi) {
    unsigned long long r;
    asm("mov.b64 %0, {%1, %2};" : "=l"(r) : "f"(lo), "f"(hi));
    return r;
}
__device__ __forceinline__ unsigned long long fma2(unsigned long long a,
                                                   unsigned long long b,
                                                   unsigned long long c) {
    unsigned long long d;
    asm("fma.rn.f32x2 %0, %1, %2, %3;" : "=l"(d) : "l"(a), "l"(b), "l"(c));
    return d;
}
__device__ __forceinline__ float2 upk2(unsigned long long v) {
    float lo, hi;
    asm("mov.b64 {%0, %1}, %2;" : "=f"(lo), "=f"(hi) : "l"(v));
    return make_float2(lo, hi);
}

__global__ __launch_bounds__(TPB, 1) void k_all(const float2* __restrict__ x,
                                                float2* __restrict__ y) {
    __shared__ __align__(16) char smem[45056];   // [0,32K) xs | [32K,44K) AUX
    __shared__ float invd[32];
    int tid = threadIdx.x;
    int blk = blockIdx.x;

    float2 (*xs)[32] = (float2(*)[32])smem;      // 128 x 32 float2, resident
    char* AUX = smem + 32768;                    // 12KB: pbuf / Rs / packed T planes

    // ================= phase 1: stage x tile, Hermitian partial Gram ========
    const float4* src = (const float4*)(x + (size_t)blk * TILE * 32);
    {
        float4* dst = (float4*)smem;
#pragma unroll
        for (int t = 0; t < 4; t++) dst[tid + TPB * t] = src[tid + TPB * t];
    }
    __syncthreads();

    {
        int gid = tid >> 8;          // m-group: rows 0-63 / 64-127
        int t8  = tid & 255;
        bool active = (t8 < 136);    // 136 upper-triangular 2x2 tiles
        int i0 = 0, j0 = 0;
        if (active) {
            int tt = t8, ti = 0;
            while (tt >= 16 - ti) { tt -= 16 - ti; ti++; }
            i0 = ti * 2;
            j0 = (ti + tt) * 2;
        }
        // packed lanes = tile rows (i0, i0+1); split +/- imag accumulators
        unsigned long long z = pk2(0.f, 0.f);
        unsigned long long re0 = z, ip0 = z, in0 = z;   // col j0
        unsigned long long re1 = z, ip1 = z, in1 = z;   // col j0+1
        if (active) {
            int mbase = gid * 64;
#pragma unroll 8
            for (int mm = 0; mm < 64; mm++) {
                float4 av = *(const float4*)&xs[mbase + mm][i0];
                float4 bv = *(const float4*)&xs[mbase + mm][j0];
                unsigned long long arr = pk2(av.x, av.z);   // re(i0), re(i0+1)
                unsigned long long aii = pk2(av.y, av.w);   // im(i0), im(i0+1)
                unsigned long long br0 = pk2(bv.x, bv.x);
                unsigned long long bi0 = pk2(bv.y, bv.y);
                unsigned long long br1 = pk2(bv.z, bv.z);
                unsigned long long bi1 = pk2(bv.w, bv.w);
                // conj(a)*b : re = ar*br + ai*bi ; im = ar*bi - ai*br
                re0 = fma2(arr, br0, fma2(aii, bi0, re0));
                ip0 = fma2(arr, bi0, ip0);
                in0 = fma2(aii, br0, in0);
                re1 = fma2(arr, br1, fma2(aii, bi1, re1));
                ip1 = fma2(arr, bi1, ip1);
                in1 = fma2(aii, br1, in1);
            }
        }
        float2 fr0 = upk2(re0), fp0 = upk2(ip0), fn0 = upk2(in0);
        float2 fr1 = upk2(re1), fp1 = upk2(ip1), fn1 = upk2(in1);
        float a00x = fr0.x, a00y = fp0.x - fn0.x;
        float a10x = fr0.y, a10y = fp0.y - fn0.y;
        float a01x = fr1.x, a01y = fp1.x - fn1.x;
        float a11x = fr1.y, a11y = fp1.y - fn1.y;

        float2* P = (float2*)AUX;    // 4 x 136 float2 combine buffer
        if (gid == 1 && active) {
            P[0 * 136 + t8] = make_float2(a00x, a00y);
            P[1 * 136 + t8] = make_float2(a01x, a01y);
            P[2 * 136 + t8] = make_float2(a10x, a10y);
            P[3 * 136 + t8] = make_float2(a11x, a11y);
        }
        __syncthreads();
        if (gid == 0 && active) {
            float2 q;
            q = P[0 * 136 + t8]; a00x += q.x; a00y += q.y;
            q = P[1 * 136 + t8]; a01x += q.x; a01y += q.y;
            q = P[2 * 136 + t8]; a10x += q.x; a10y += q.y;
            q = P[3 * 136 + t8]; a11x += q.x; a11y += q.y;
            float4* out = g_partial4[blk];
            out[t8 * 2]     = make_float4(a00x, a00y, a01x, a01y);
            out[t8 * 2 + 1] = make_float4(a10x, a10y, a11x, a11y);
        }
    }

    __threadfence();          // release partial stores
    __syncthreads();
    unsigned rep = 0;
    if (tid == 0) {
        unsigned v = atomicAdd(&g_arrive, 1u);
        rep = (v >> 7) + 1u;  // launch index; arrive target = rep*128
    }

    // ============ distributed reduce: 17 blocks, warp-per-element ===========
    if (blk < NRED) {
        if (tid == 0) {
            unsigned target = rep << 7;
            while ((int)(*(volatile unsigned*)&g_arrive - target) < 0) { }
            __threadfence();  // acquire partials
        }
        __syncthreads();
        int w = tid >> 5, l = tid & 31;
        int e = blk * 16 + w;                       // 0..271
        const float4* gp4 = (const float4*)g_partial4;
        float4 p  = gp4[(size_t)l * 272 + e];
        float4 q1 = gp4[(size_t)(l + 32) * 272 + e];
        float4 q2 = gp4[(size_t)(l + 64) * 272 + e];
        float4 q3 = gp4[(size_t)(l + 96) * 272 + e];
        p.x = ((p.x + q1.x) + q2.x) + q3.x;
        p.y = ((p.y + q1.y) + q2.y) + q3.y;
        p.z = ((p.z + q1.z) + q2.z) + q3.z;
        p.w = ((p.w + q1.w) + q2.w) + q3.w;
#pragma unroll
        for (int off = 16; off > 0; off >>= 1) {
            p.x += __shfl_xor_sync(0xffffffffu, p.x, off);
            p.y += __shfl_xor_sync(0xffffffffu, p.y, off);
            p.z += __shfl_xor_sync(0xffffffffu, p.z, off);
            p.w += __shfl_xor_sync(0xffffffffu, p.w, off);
        }
        if (l == 0) g_gram4[e] = p;
        __threadfence();
        __syncthreads();
        if (tid == 0) atomicAdd(&g_reddone, 1u);
    }

    // ================= phase 2: block 0 solve ===============================
    if (blk == 0) {
        if (tid == 0) {
            unsigned target = rep * NRED;
            while ((int)(*(volatile unsigned*)&g_reddone - target) < 0) { }
            __threadfence();  // acquire g_gram
        }
        __syncthreads();
        // overlays: Gs = xs rows 0..31, Ss = xs rows 32..63, Rs = AUX
        float2 (*Gs)[32] = (float2(*)[32])smem;
        float2 (*Ss)[32] = (float2(*)[32])(smem + 8192);
        float2 (*Rs)[32] = (float2(*)[32])AUX;

        // load + Hermitian mirror G into smem
        if (tid < 136) {
            int tt = tid, ti = 0;
            while (tt >= 16 - ti) { tt -= 16 - ti; ti++; }
            int i0 = ti * 2;
            int j0 = (ti + tt) * 2;
            float4 v0 = g_gram4[tid * 2];
            float4 v1 = g_gram4[tid * 2 + 1];
            Gs[i0][j0]         = make_float2(v0.x, v0.y);
            Gs[i0][j0 + 1]     = make_float2(v0.z, v0.w);
            Gs[i0 + 1][j0]     = make_float2(v1.x, v1.y);
            Gs[i0 + 1][j0 + 1] = make_float2(v1.z, v1.w);
            if (i0 != j0) {
                Gs[j0][i0]         = make_float2(v0.x, -v0.y);
                Gs[j0][i0 + 1]     = make_float2(v1.x, -v1.y);
                Gs[j0 + 1][i0]     = make_float2(v0.z, -v0.w);
                Gs[j0 + 1][i0 + 1] = make_float2(v1.z, -v1.w);
            }
        }
        __syncthreads();

        // ---- register+shfl Cholesky (upper), warp 0, lane = column k -------
        if (tid < 32) {
            int k = tid;
            float2 a[32];
#pragma unroll
            for (int i = 0; i < 32; i++) a[i] = Gs[i][k];
#pragma unroll
            for (int j = 0; j < 32; j++) {
                float d = __shfl_sync(0xffffffffu, a[j].x, j) + EPSV;
                float inv = rsqrtf(d);
                float rjj = d * inv;                       // sqrt(d)
                float rx, ry;
                if (k > j)       { rx = a[j].x * inv; ry = a[j].y * inv; }
                else if (k == j) { rx = rjj; ry = 0.f; invd[j] = inv; }
                else             { rx = 0.f; ry = 0.f; }
                Rs[j][k] = make_float2(rx, ry);
                // a[i] -= conj(R[j][i]) * R[j][k]  for i > j
#pragma unroll
                for (int i = j + 1; i < 32; i++) {
                    float bx = __shfl_sync(0xffffffffu, rx, i);
                    float by = __shfl_sync(0xffffffffu, ry, i);
                    a[i].x -= bx * rx + by * ry;
                    a[i].y -= bx * ry - by * rx;
                }
            }
        }
        __syncthreads();

        // ---- register back-substitution: S11 (lanes 0-15), S22 (16-31) ----
        if (tid < 32) {
            int half = tid >> 4;
            int j = tid & 15;
            int base = half * 16;
            float2 s[16];
#pragma unroll
            for (int i = 15; i >= 0; i--) {
                if (i == j) {
                    s[i] = make_float2(invd[base + i], 0.f);
                } else if (i < j) {
                    float ax = 0.f, ay = 0.f;
#pragma unroll
                    for (int k = i + 1; k < 16; k++) {
                        float2 sv = (k <= j) ? s[k] : make_float2(0.f, 0.f);
                        float2 rv = Rs[base + i][base + k];
                        ax += rv.x * sv.x - rv.y * sv.y;
                        ay += rv.x * sv.y + rv.y * sv.x;
                    }
                    float inv = invd[base + i];
                    s[i] = make_float2(-ax * inv, -ay * inv);
                }
            }
#pragma unroll
            for (int i = 0; i < 16; i++)
                if (i <= j) Ss[base + i][base + j] = s[i];
        }
        __syncthreads();

        // Tmp = R12 * S22   (S22 upper-tri: k <= j; unrolled + predicated)
        float2 (*Tmp)[16] = (float2(*)[16])smem;
        if (tid < 256) {
            int i = tid >> 4, j = tid & 15;
            float ax = 0.f, ay = 0.f;
#pragma unroll
            for (int k = 0; k < 16; k++) {
                if (k <= j) {
                    float2 rv = Rs[i][16 + k];
                    float2 sv = Ss[16 + k][16 + j];
                    ax += rv.x * sv.x - rv.y * sv.y;
                    ay += rv.x * sv.y + rv.y * sv.x;
                }
            }
            Tmp[i][j] = make_float2(ax, ay);
        }
        __syncthreads();
        // S12 = -S11 * Tmp   (S11 upper-tri: k >= i; unrolled + predicated)
        if (tid < 256) {
            int i = tid >> 4, j = tid & 15;
            float ax = 0.f, ay = 0.f;
#pragma unroll
            for (int k = 0; k < 16; k++) {
                if (k >= i) {
                    float2 sv = Ss[i][k];
                    float2 tv = Tmp[k][j];
                    ax += sv.x * tv.x - sv.y * tv.y;
                    ay += sv.x * tv.y + sv.y * tv.x;
                }
            }
            Ss[i][16 + j] = make_float2(-ax, -ay);
        }
        __syncthreads();

        // write T (lower triangle = 0)
        for (int t = tid; t < 1024; t += TPB) {
            int r = t >> 5, c = t & 31;
            g_T[t] = (r <= c) ? Ss[r][c] : make_float2(0.f, 0.f);
        }
        __threadfence();
        __syncthreads();
        if (tid == 0) atomicAdd(&g_tready, 1u);

        // reload xs rows 0..63 (clobbered by Gs/Ss/Tmp); rows 64..127 intact
        ((float4*)smem)[tid]       = src[tid];
        ((float4*)smem)[tid + 512] = src[tid + 512];
    } else {
        if (tid == 0) {
            while ((int)(*(volatile unsigned*)&g_tready - rep) < 0) { }
            __threadfence();  // acquire T
        }
        __syncthreads();
    }

    // ================= phase 3: apply  Y = X * T  (packed f32x2) ============
    {
        unsigned long long (*P1)[32] = (unsigned long long(*)[32])AUX;           // (tr0,tr1)
        unsigned long long (*P2)[32] = (unsigned long long(*)[32])(AUX + 4096);  // (ti0,ti1)
        unsigned long long (*P3)[32] = (unsigned long long(*)[32])(AUX + 8192);  // (-ti0,-ti1)
        {
            int k2 = tid >> 5, jj = tid & 31;   // 512 threads = 16 k-pairs x 32 cols
            float2 v0 = g_T[(2 * k2) * 32 + jj];
            float2 v1 = g_T[(2 * k2 + 1) * 32 + jj];
            P1[k2][jj] = pk2(v0.x, v1.x);
            P2[k2][jj] = pk2(v0.y, v1.y);
            P3[k2][jj] = pk2(-v0.y, -v1.y);
        }
        __syncthreads();

        int j  = tid & 31;
        int r0 = (tid >> 5) * 8;   // 16 warps x 8 rows = 128 rows

        unsigned long long accx[8], accy[8];
        unsigned long long z = pk2(0.f, 0.f);
#pragma unroll
        for (int r = 0; r < 8; r++) { accx[r] = z; accy[r] = z; }

#pragma unroll
        for (int k2 = 0; k2 < 16; k2++) {
            unsigned long long p1 = P1[k2][j];
            unsigned long long p2 = P2[k2][j];
            unsigned long long p3 = P3[k2][j];
#pragma unroll
            for (int r = 0; r < 8; r++) {
                float4 a = *(const float4*)&xs[r0 + r][2 * k2];  // (re0,im0,re1,im1)
                unsigned long long arr = pk2(a.x, a.z);
                unsigned long long aii = pk2(a.y, a.w);
                accx[r] = fma2(arr, p1, accx[r]);
                accx[r] = fma2(aii, p3, accx[r]);
                accy[r] = fma2(arr, p2, accy[r]);
                accy[r] = fma2(aii, p1, accy[r]);
            }
        }

        size_t base = (size_t)blk * TILE + r0;
#pragma unroll
        for (int r = 0; r < 8; r++) {
            float2 fx = upk2(accx[r]);
            float2 fy = upk2(accy[r]);
            y[(base + r) * 32 + j] = make_float2(fx.x + fx.y, fy.x + fy.y);
        }
    }
}

// ---------------------------------------------------------------------------
extern "C" void kernel_launch(void* const* d_in, const int* in_sizes, int n_in,
                              void* d_out, int out_size) {
    const float2* x = (const float2*)d_in[0];
    float2* y = (float2*)d_out;
    (void)in_sizes; (void)n_in; (void)out_size;

    k_all<<<NBLK, TPB>>>(x, y);
}

// round 16
// speedup vs baseline: 1.2513x; 1.0570x over previous
#include <cuda_runtime.h>

#define NBLK 128
#define TPB  512
#define TILE 128
#define NRED 17          // reducer blocks; 17*16 = 272 float4 elements
#define EPSV 1e-10f

__device__ __align__(16) float4 g_partial4[NBLK][272];   // 136 tiles x 2 float4
__device__ __align__(16) float2 g_gramF[1024];           // full mirrored 32x32 Gram
__device__ unsigned g_arrive;    // monotonic; +128 per launch
__device__ unsigned g_reddone;   // monotonic; +17  per launch

__device__ __forceinline__ unsigned long long pk2(float lo, float hi) {
    unsigned long long r;
    asm("mov.b64 %0, {%1, %2};" : "=l"(r) : "f"(lo), "f"(hi));
    return r;
}
__device__ __forceinline__ unsigned long long fma2(unsigned long long a,
                                                   unsigned long long b,
                                                   unsigned long long c) {
    unsigned long long d;
    asm("fma.rn.f32x2 %0, %1, %2, %3;" : "=l"(d) : "l"(a), "l"(b), "l"(c));
    return d;
}
__device__ __forceinline__ float2 upk2(unsigned long long v) {
    float lo, hi;
    asm("mov.b64 {%0, %1}, %2;" : "=f"(lo), "=f"(hi) : "l"(v));
    return make_float2(lo, hi);
}

__global__ __launch_bounds__(TPB, 1) void k_all(const float2* __restrict__ x,
                                                float2* __restrict__ y) {
    __shared__ __align__(16) char smem[49152];   // [0,32K) xs | [32K,48K) AUX
    int tid = threadIdx.x;
    int blk = blockIdx.x;

    float2 (*xs)[32] = (float2(*)[32])smem;      // 128 x 32 float2, resident
    char* AUX = smem + 32768;                    // 16KB: pbuf / Rs+Ss / P planes

    // ================= phase 1: stage x tile, Hermitian partial Gram ========
    const float4* src = (const float4*)(x + (size_t)blk * TILE * 32);
    {
        float4* dst = (float4*)smem;
#pragma unroll
        for (int t = 0; t < 4; t++) dst[tid + TPB * t] = src[tid + TPB * t];
    }
    __syncthreads();

    {
        // flat jobs 0..271: job = tile + 136*mgroup  -> active warps 0..8,
        // busiest SMSP carries 3 warps (was 4 with the gid split).
        bool active = (tid < 272);
        int tile = (tid < 136) ? tid : tid - 136;
        int mg   = (tid < 136) ? 0 : 1;
        int i0 = 0, j0 = 0;
        if (active) {
            int tt = tile, ti = 0;
            while (tt >= 16 - ti) { tt -= 16 - ti; ti++; }
            i0 = ti * 2;
            j0 = (ti + tt) * 2;
        }
        float a00x = 0.f, a00y = 0.f, a01x = 0.f, a01y = 0.f;
        float a10x = 0.f, a10y = 0.f, a11x = 0.f, a11y = 0.f;
        if (active) {
            int mbase = mg * 64;
#pragma unroll 8
            for (int mm = 0; mm < 64; mm++) {
                float4 av = *(const float4*)&xs[mbase + mm][i0];
                float4 bv = *(const float4*)&xs[mbase + mm][j0];
                a00x += av.x * bv.x + av.y * bv.y;  a00y += av.x * bv.y - av.y * bv.x;
                a01x += av.x * bv.z + av.y * bv.w;  a01y += av.x * bv.w - av.y * bv.z;
                a10x += av.z * bv.x + av.w * bv.y;  a10y += av.z * bv.y - av.w * bv.x;
                a11x += av.z * bv.z + av.w * bv.w;  a11y += av.z * bv.w - av.w * bv.z;
            }
        }
        float2* P = (float2*)AUX;    // 4 x 136 float2 combine buffer
        if (active && mg == 1) {
            P[0 * 136 + tile] = make_float2(a00x, a00y);
            P[1 * 136 + tile] = make_float2(a01x, a01y);
            P[2 * 136 + tile] = make_float2(a10x, a10y);
            P[3 * 136 + tile] = make_float2(a11x, a11y);
        }
        __syncthreads();
        if (active && mg == 0) {
            float2 q;
            q = P[0 * 136 + tile]; a00x += q.x; a00y += q.y;
            q = P[1 * 136 + tile]; a01x += q.x; a01y += q.y;
            q = P[2 * 136 + tile]; a10x += q.x; a10y += q.y;
            q = P[3 * 136 + tile]; a11x += q.x; a11y += q.y;
            float4* out = g_partial4[blk];
            out[tile * 2]     = make_float4(a00x, a00y, a01x, a01y);
            out[tile * 2 + 1] = make_float4(a10x, a10y, a11x, a11y);
        }
    }

    __threadfence();          // release partial stores
    __syncthreads();
    unsigned rep = 0;
    if (tid == 0) {
        unsigned v = atomicAdd(&g_arrive, 1u);
        rep = (v >> 7) + 1u;  // launch index; arrive target = rep*128
    }

    // ======= distributed reduce: 17 blocks, warp-per-element, mirrored ======
    if (blk < NRED) {
        if (tid == 0) {
            unsigned target = rep << 7;
            while ((int)(*(volatile unsigned*)&g_arrive - target) < 0) { }
            __threadfence();  // acquire partials
        }
        __syncthreads();
        int w = tid >> 5, l = tid & 31;
        int e = blk * 16 + w;                       // 0..271
        const float4* gp4 = (const float4*)g_partial4;
        float4 p  = gp4[(size_t)l * 272 + e];
        float4 q1 = gp4[(size_t)(l + 32) * 272 + e];
        float4 q2 = gp4[(size_t)(l + 64) * 272 + e];
        float4 q3 = gp4[(size_t)(l + 96) * 272 + e];
        p.x = ((p.x + q1.x) + q2.x) + q3.x;
        p.y = ((p.y + q1.y) + q2.y) + q3.y;
        p.z = ((p.z + q1.z) + q2.z) + q3.z;
        p.w = ((p.w + q1.w) + q2.w) + q3.w;
#pragma unroll
        for (int off = 16; off > 0; off >>= 1) {
            p.x += __shfl_xor_sync(0xffffffffu, p.x, off);
            p.y += __shfl_xor_sync(0xffffffffu, p.y, off);
            p.z += __shfl_xor_sync(0xffffffffu, p.z, off);
            p.w += __shfl_xor_sync(0xffffffffu, p.w, off);
        }
        if (l == 0) {
            // e = tile L, row half h; write direct + Hermitian mirror
            int L = e >> 1, h = e & 1;
            int tt = L, ti = 0;
            while (tt >= 16 - ti) { tt -= 16 - ti; ti++; }
            int tj = ti + tt;
            int i  = 2 * ti + h;
            int j0 = 2 * tj;
            g_gramF[i * 32 + j0]       = make_float2(p.x, p.y);
            g_gramF[i * 32 + j0 + 1]   = make_float2(p.z, p.w);
            g_gramF[j0 * 32 + i]       = make_float2(p.x, -p.y);
            g_gramF[(j0 + 1) * 32 + i] = make_float2(p.z, -p.w);
        }
        __threadfence();
        __syncthreads();
        if (tid == 0) atomicAdd(&g_reddone, 1u);
    }

    // ================= every block: wait for Gram, solve locally ============
    if (tid == 0) {
        unsigned target = rep * NRED;
        while ((int)(*(volatile unsigned*)&g_reddone - target) < 0) { }
        __threadfence();  // acquire g_gramF
    }
    __syncthreads();

    float2 (*Rs)[32] = (float2(*)[32])AUX;             // 8KB
    float2 (*Ss)[32] = (float2(*)[32])(AUX + 8192);    // 8KB; Tmp lives in
                                                       // Ss rows 16-31 cols 0-15
    // ---- register+shfl Cholesky (upper), warp 0, lane = column k ----------
    if (tid < 32) {
        int k = tid;
        float2 a[32];
#pragma unroll
        for (int i = 0; i < 32; i++) a[i] = g_gramF[i * 32 + k];   // coalesced
#pragma unroll
        for (int j = 0; j < 32; j++) {
            float d = __shfl_sync(0xffffffffu, a[j].x, j) + EPSV;
            float inv = rsqrtf(d);
            float rjj = d * inv;                       // sqrt(d)
            float rx, ry;
            if (k > j)       { rx = a[j].x * inv; ry = a[j].y * inv; }
            else if (k == j) { rx = rjj; ry = 0.f; }
            else             { rx = 0.f; ry = 0.f; }
            // diag slot stashes inv in .y (never read as a matrix entry)
            Rs[j][k] = (k == j) ? make_float2(rjj, inv) : make_float2(rx, ry);
            // a[i] -= conj(R[j][i]) * R[j][k]  for i > j
#pragma unroll
            for (int i = j + 1; i < 32; i++) {
                float bx = __shfl_sync(0xffffffffu, rx, i);
                float by = __shfl_sync(0xffffffffu, ry, i);
                a[i].x -= bx * rx + by * ry;
                a[i].y -= bx * ry - by * rx;
            }
        }
    }
    __syncthreads();

    // ---- register back-substitution: S11 (lanes 0-15), S22 (16-31) --------
    if (tid < 32) {
        int half = tid >> 4;
        int j = tid & 15;
        int base = half * 16;
        float2 s[16];
#pragma unroll
        for (int i = 15; i >= 0; i--) {
            if (i == j) {
                s[i] = make_float2(Rs[base + i][base + i].y, 0.f);   // invd
            } else if (i < j) {
                float ax = 0.f, ay = 0.f;
#pragma unroll
                for (int k = i + 1; k < 16; k++) {
                    float2 sv = (k <= j) ? s[k] : make_float2(0.f, 0.f);
                    float2 rv = Rs[base + i][base + k];
                    ax += rv.x * sv.x - rv.y * sv.y;
                    ay += rv.x * sv.y + rv.y * sv.x;
                }
                float inv = Rs[base + i][base + i].y;
                s[i] = make_float2(-ax * inv, -ay * inv);
            }
        }
#pragma unroll
        for (int i = 0; i < 16; i++)
            if (i <= j) Ss[base + i][base + j] = s[i];
    }
    __syncthreads();

    // Tmp = R12 * S22  (Tmp(i,j) -> Ss[16+i][j], unused lower-left quadrant)
    if (tid < 256) {
        int i = tid >> 4, j = tid & 15;
        float ax = 0.f, ay = 0.f;
#pragma unroll
        for (int k = 0; k < 16; k++) {
            if (k <= j) {                      // S22 upper-triangular
                float2 rv = Rs[i][16 + k];
                float2 sv = Ss[16 + k][16 + j];
                ax += rv.x * sv.x - rv.y * sv.y;
                ay += rv.x * sv.y + rv.y * sv.x;
            }
        }
        Ss[16 + i][j] = make_float2(ax, ay);
    }
    __syncthreads();
    // S12 = -S11 * Tmp
    if (tid < 256) {
        int i = tid >> 4, j = tid & 15;
        float ax = 0.f, ay = 0.f;
#pragma unroll
        for (int k = 0; k < 16; k++) {
            if (k >= i) {                      // S11 upper-triangular
                float2 sv = Ss[i][k];
                float2 tv = Ss[16 + k][j];     // Tmp
                ax += sv.x * tv.x - sv.y * tv.y;
                ay += sv.x * tv.y + sv.y * tv.x;
            }
        }
        Ss[i][16 + j] = make_float2(-ax, -ay);
    }
    __syncthreads();

    // ================= phase 3: pack T planes, apply Y = X * T ==============
    {
        unsigned long long (*P1)[32] = (unsigned long long(*)[32])AUX;           // (tr0,tr1)
        unsigned long long (*P2)[32] = (unsigned long long(*)[32])(AUX + 4096);  // (ti0,ti1)
        unsigned long long (*P3)[32] = (unsigned long long(*)[32])(AUX + 8192);  // (-ti0,-ti1)
        {
            int k2 = tid >> 5, jj = tid & 31;   // 16 k-pairs x 32 cols
            int rlo = 2 * k2, rhi = 2 * k2 + 1;
            float2 v0 = (rlo <= jj) ? Ss[rlo][jj] : make_float2(0.f, 0.f);
            float2 v1 = (rhi <= jj) ? Ss[rhi][jj] : make_float2(0.f, 0.f);
            __syncthreads();                    // all T reads done before overlay
            P1[k2][jj] = pk2(v0.x, v1.x);
            P2[k2][jj] = pk2(v0.y, v1.y);
            P3[k2][jj] = pk2(-v0.y, -v1.y);
        }
        __syncthreads();

        int j  = tid & 31;
        int r0 = (tid >> 5) * 8;   // 16 warps x 8 rows = 128 rows

        unsigned long long accx[8], accy[8];
        unsigned long long z = pk2(0.f, 0.f);
#pragma unroll
        for (int r = 0; r < 8; r++) { accx[r] = z; accy[r] = z; }

#pragma unroll
        for (int k2 = 0; k2 < 16; k2++) {
            unsigned long long p1 = P1[k2][j];
            unsigned long long p2 = P2[k2][j];
            unsigned long long p3 = P3[k2][j];
#pragma unroll
            for (int r = 0; r < 8; r++) {
                float4 a = *(const float4*)&xs[r0 + r][2 * k2];  // (re0,im0,re1,im1)
                unsigned long long arr = pk2(a.x, a.z);
                unsigned long long aii = pk2(a.y, a.w);
                accx[r] = fma2(arr, p1, accx[r]);
                accx[r] = fma2(aii, p3, accx[r]);
                accy[r] = fma2(arr, p2, accy[r]);
                accy[r] = fma2(aii, p1, accy[r]);
            }
        }

        size_t base = (size_t)blk * TILE + r0;
#pragma unroll
        for (int r = 0; r < 8; r++) {
            float2 fx = upk2(accx[r]);
            float2 fy = upk2(accy[r]);
            y[(base + r) * 32 + j] = make_float2(fx.x + fx.y, fy.x + fy.y);
        }
    }
}

// ---------------------------------------------------------------------------
extern "C" void kernel_launch(void* const* d_in, const int* in_sizes, int n_in,
                              void* d_out, int out_size) {
    const float2* x = (const float2*)d_in[0];
    float2* y = (float2*)d_out;
    (void)in_sizes; (void)n_in; (void)out_size;

    k_all<<<NBLK, TPB>>>(x, y);
}